// round 2
// baseline (speedup 1.0000x reference)
#include <cuda_runtime.h>
#include <math.h>

#define Bv 8
#define Tv 128
#define Nv 256
#define Fv 128
#define M_TOT (Bv*Tv*Nv)   // 262144

// -------- scratch (device globals: allowed; no runtime allocation) --------
__device__ float g_q   [M_TOT*Fv];
__device__ float g_kh  [M_TOT*Fv];
__device__ float g_vh  [M_TOT*Fv];
__device__ float g_attn[M_TOT*Fv];
__device__ float g_ln1 [M_TOT*Fv];

// =====================================================================
// Kernel 1: q/kh/vh projections.  C[128tile,128] = (X + te) @ W + b (relu?)
// grid: (M/128, 3), 256 threads, 8x8 microtile per thread.
// =====================================================================
__global__ __launch_bounds__(256) void qkv_kernel(
    const float* __restrict__ xl, const float* __restrict__ xh,
    const float* __restrict__ te,
    const float* __restrict__ Wq,  const float* __restrict__ bq,
    const float* __restrict__ Wkh, const float* __restrict__ bkh,
    const float* __restrict__ Wvh, const float* __restrict__ bvh)
{
    extern __shared__ float sm[];
    float* As = sm;             // 128*128
    float* Ws = sm + 16384;     // 128*128

    const float *X, *W, *bias; float* out; int doRelu;
    if (blockIdx.y == 0)      { X = xl; W = Wq;  bias = bq;  out = g_q;  doRelu = 0; }
    else if (blockIdx.y == 1) { X = xh; W = Wkh; bias = bkh; out = g_kh; doRelu = 1; }
    else                      { X = xh; W = Wvh; bias = bvh; out = g_vh; doRelu = 1; }

    const int m0 = blockIdx.x * 128;
    const float* teRow = te + (m0 / Nv) * Fv;   // tile spans a single (b,t)
    const int tid = threadIdx.x;

    for (int v = tid; v < 4096; v += 256)
        ((float4*)Ws)[v] = ((const float4*)W)[v];
    for (int v = tid; v < 4096; v += 256) {
        int row = v >> 5, c4 = v & 31;
        float4 a  = ((const float4*)(X + (m0 + row) * Fv))[c4];
        float4 t4 = ((const float4*)teRow)[c4];
        a.x += t4.x; a.y += t4.y; a.z += t4.z; a.w += t4.w;
        ((float4*)(As + row * Fv))[c4] = a;
    }
    __syncthreads();

    const int ty = tid >> 4, tx = tid & 15;
    float acc[8][8];
    #pragma unroll
    for (int r = 0; r < 8; ++r)
        #pragma unroll
        for (int c = 0; c < 8; ++c) acc[r][c] = 0.f;

    #pragma unroll 1
    for (int k4 = 0; k4 < 32; ++k4) {
        float4 a4[8];
        #pragma unroll
        for (int r = 0; r < 8; ++r)
            a4[r] = ((const float4*)(As + (ty*8 + r) * Fv))[k4];
        #pragma unroll
        for (int kk = 0; kk < 4; ++kk) {
            const float* wrow = Ws + (k4*4 + kk) * Fv + tx*8;
            float4 b0 = *(const float4*)wrow;
            float4 b1 = *(const float4*)(wrow + 4);
            #pragma unroll
            for (int r = 0; r < 8; ++r) {
                float a = kk==0 ? a4[r].x : kk==1 ? a4[r].y : kk==2 ? a4[r].z : a4[r].w;
                acc[r][0] += a*b0.x; acc[r][1] += a*b0.y; acc[r][2] += a*b0.z; acc[r][3] += a*b0.w;
                acc[r][4] += a*b1.x; acc[r][5] += a*b1.y; acc[r][6] += a*b1.z; acc[r][7] += a*b1.w;
            }
        }
    }

    float bv[8];
    #pragma unroll
    for (int c = 0; c < 8; ++c) bv[c] = bias[tx*8 + c];
    #pragma unroll
    for (int r = 0; r < 8; ++r) {
        float* orow = out + (m0 + ty*8 + r) * Fv + tx*8;
        float o[8];
        #pragma unroll
        for (int c = 0; c < 8; ++c) {
            o[c] = acc[r][c] + bv[c];
            if (doRelu) o[c] = fmaxf(o[c], 0.f);
        }
        *(float4*)orow       = make_float4(o[0], o[1], o[2], o[3]);
        *(float4*)(orow + 4) = make_float4(o[4], o[5], o[6], o[7]);
    }
}

// =====================================================================
// Kernel 2: per-(b,n) causal temporal attention. One head per block.
// =====================================================================
template<int NJ>
__device__ __forceinline__ void attn_scores(const float* __restrict__ Ks,
                                            const float* __restrict__ qw,
                                            int lane, float sc[8][4])
{
    #pragma unroll 1
    for (int k4 = 0; k4 < 32; ++k4) {
        float4 kf[NJ];
        #pragma unroll
        for (int j = 0; j < NJ; ++j)
            kf[j] = *(const float4*)(Ks + (lane + 32*j) * 132 + k4*4);
        #pragma unroll
        for (int r = 0; r < 8; ++r) {
            float4 qf = *(const float4*)(qw + r * 132 + k4*4);
            #pragma unroll
            for (int j = 0; j < NJ; ++j) {
                sc[r][j] += qf.x * kf[j].x;
                sc[r][j] += qf.y * kf[j].y;
                sc[r][j] += qf.z * kf[j].z;
                sc[r][j] += qf.w * kf[j].w;
            }
        }
    }
}

__global__ __launch_bounds__(256) void attn_kernel()
{
    extern __shared__ float sm[];
    float* Ks = sm;                    // 128*132
    float* Vs = Ks + 128*132;          // 128*132
    float* qs = Vs + 128*132;          // 8 warps * 8 rows * 132
    float* ps = qs + 8*8*132;          // 8 warps * 8 rows * 128

    const int head = blockIdx.x;
    const int b = head >> 8;           // / 256
    const int n = head & 255;
    const int base = b * Tv * Nv + n;  // row index at t=0; row(t)=base+t*Nv

    const int tid = threadIdx.x, w = tid >> 5, lane = tid & 31;

    for (int s = w; s < Tv; s += 8) {
        int off = (base + s * Nv) * Fv;
        ((float4*)(Ks + s*132))[lane] = ((const float4*)(g_kh + off))[lane];
        ((float4*)(Vs + s*132))[lane] = ((const float4*)(g_vh + off))[lane];
    }
    __syncthreads();

    float* qw = qs + w * 8 * 132;
    float* pw = ps + w * 8 * 128;
    const float scale = 0.08838834764831845f;   // 1/sqrt(128)

    for (int g = 0; g < 2; ++g) {
        const int tbase = w * 16 + g * 8;

        #pragma unroll
        for (int r = 0; r < 8; ++r) {
            int off = (base + (tbase + r) * Nv) * Fv;
            ((float4*)(qw + r*132))[lane] = ((const float4*)(g_q + off))[lane];
        }
        __syncwarp();

        float sc[8][4];
        #pragma unroll
        for (int r = 0; r < 8; ++r) { sc[r][0]=sc[r][1]=sc[r][2]=sc[r][3]=0.f; }

        const int njv = (tbase + 39) >> 5;   // causal: only j with lane+32j possibly <= t
        switch (njv) {
            case 1:  attn_scores<1>(Ks, qw, lane, sc); break;
            case 2:  attn_scores<2>(Ks, qw, lane, sc); break;
            case 3:  attn_scores<3>(Ks, qw, lane, sc); break;
            default: attn_scores<4>(Ks, qw, lane, sc); break;
        }

        #pragma unroll
        for (int r = 0; r < 8; ++r) {
            const int t = tbase + r;
            float mx = -1e30f;
            #pragma unroll
            for (int j = 0; j < 4; ++j) {
                int s = lane + 32*j;
                float v = (s <= t) ? sc[r][j] * scale : -1e30f;
                sc[r][j] = v;
                mx = fmaxf(mx, v);
            }
            #pragma unroll
            for (int o = 16; o; o >>= 1) mx = fmaxf(mx, __shfl_xor_sync(0xffffffffu, mx, o));
            float sum = 0.f;
            #pragma unroll
            for (int j = 0; j < 4; ++j) { float e = __expf(sc[r][j] - mx); sc[r][j] = e; sum += e; }
            #pragma unroll
            for (int o = 16; o; o >>= 1) sum += __shfl_xor_sync(0xffffffffu, sum, o);
            float inv = 1.f / sum;
            #pragma unroll
            for (int j = 0; j < 4; ++j) pw[r*128 + lane + 32*j] = sc[r][j] * inv;
        }
        __syncwarp();

        float4 o[8];
        #pragma unroll
        for (int r = 0; r < 8; ++r) o[r] = make_float4(0.f, 0.f, 0.f, 0.f);
        const int smax = tbase + 8;               // causal: p==0 beyond this
        for (int s = 0; s < smax; ++s) {
            float4 vv = *(const float4*)(Vs + s*132 + 4*lane);
            #pragma unroll
            for (int r = 0; r < 8; ++r) {
                float p = pw[r*128 + s];
                o[r].x += p*vv.x; o[r].y += p*vv.y; o[r].z += p*vv.z; o[r].w += p*vv.w;
            }
        }
        #pragma unroll
        for (int r = 0; r < 8; ++r) {
            int off = (base + (tbase + r) * Nv) * Fv;
            ((float4*)(g_attn + off))[lane] = o[r];
        }
        __syncwarp();
    }
}

// =====================================================================
// Kernel 3: val = attn @ Wo + bo + (xl + te); ln1 = LayerNorm(val)
// =====================================================================
__global__ __launch_bounds__(256) void proj_kernel(
    const float* __restrict__ xl, const float* __restrict__ te,
    const float* __restrict__ Wo, const float* __restrict__ bo)
{
    extern __shared__ float sm[];
    float* As = sm;
    float* Ws = sm + 16384;

    const int m0 = blockIdx.x * 128;
    const float* teRow = te + (m0 / Nv) * Fv;
    const int tid = threadIdx.x;

    for (int v = tid; v < 4096; v += 256)
        ((float4*)Ws)[v] = ((const float4*)Wo)[v];
    for (int v = tid; v < 4096; v += 256) {
        int row = v >> 5, c4 = v & 31;
        ((float4*)(As + row * Fv))[c4] = ((const float4*)(g_attn + (m0 + row) * Fv))[c4];
    }
    __syncthreads();

    const int ty = tid >> 4, tx = tid & 15;
    float acc[8][8];
    #pragma unroll
    for (int r = 0; r < 8; ++r)
        #pragma unroll
        for (int c = 0; c < 8; ++c) acc[r][c] = 0.f;

    #pragma unroll 1
    for (int k4 = 0; k4 < 32; ++k4) {
        float4 a4[8];
        #pragma unroll
        for (int r = 0; r < 8; ++r)
            a4[r] = ((const float4*)(As + (ty*8 + r) * Fv))[k4];
        #pragma unroll
        for (int kk = 0; kk < 4; ++kk) {
            const float* wrow = Ws + (k4*4 + kk) * Fv + tx*8;
            float4 b0 = *(const float4*)wrow;
            float4 b1 = *(const float4*)(wrow + 4);
            #pragma unroll
            for (int r = 0; r < 8; ++r) {
                float a = kk==0 ? a4[r].x : kk==1 ? a4[r].y : kk==2 ? a4[r].z : a4[r].w;
                acc[r][0] += a*b0.x; acc[r][1] += a*b0.y; acc[r][2] += a*b0.z; acc[r][3] += a*b0.w;
                acc[r][4] += a*b1.x; acc[r][5] += a*b1.y; acc[r][6] += a*b1.z; acc[r][7] += a*b1.w;
            }
        }
    }

    float bv[8];
    #pragma unroll
    for (int c = 0; c < 8; ++c) bv[c] = bo[tx*8 + c];
    __syncthreads();   // all As reads done before restaging

    #pragma unroll
    for (int r = 0; r < 8; ++r) {
        int grow = m0 + ty*8 + r;
        const float* xrow = xl + grow * Fv + tx*8;
        const float* trow = teRow + tx*8;
        #pragma unroll
        for (int c = 0; c < 8; ++c)
            As[(ty*8 + r) * Fv + tx*8 + c] = acc[r][c] + bv[c] + xrow[c] + trow[c];
    }
    __syncthreads();

    const int w = tid >> 5, lane = tid & 31;
    for (int row = w; row < 128; row += 8) {
        float4 v = ((const float4*)(As + row * Fv))[lane];
        float s  = v.x + v.y + v.z + v.w;
        float s2 = v.x*v.x + v.y*v.y + v.z*v.z + v.w*v.w;
        #pragma unroll
        for (int o = 16; o; o >>= 1) {
            s  += __shfl_xor_sync(0xffffffffu, s,  o);
            s2 += __shfl_xor_sync(0xffffffffu, s2, o);
        }
        float mean = s * 0.0078125f;
        float var  = s2 * 0.0078125f - mean * mean;
        float rs   = rsqrtf(var + 1e-5f);
        float4 ov = make_float4((v.x-mean)*rs, (v.y-mean)*rs, (v.z-mean)*rs, (v.w-mean)*rs);
        ((float4*)(g_ln1 + (m0 + row) * Fv))[lane] = ov;
    }
}

// =====================================================================
// Kernel 4: h = relu(ln1@Wf1+bf1); h2 = h@Wf2+bf2; out = LN(h2 + ln1)
// TILE_M = 64; both weights resident in smem; fused in one pass.
// =====================================================================
__global__ __launch_bounds__(256) void ffn_kernel(
    float* __restrict__ outp,
    const float* __restrict__ Wf1, const float* __restrict__ bf1,
    const float* __restrict__ Wf2, const float* __restrict__ bf2)
{
    extern __shared__ float sm[];
    float* As  = sm;            // 64*128 (ln1 tile, kept for residual)
    float* Hs  = sm + 8192;     // 64*128 (h tile, then final staging)
    float* W1s = sm + 16384;    // 128*128
    float* W2s = sm + 32768;    // 128*128

    const int m0 = blockIdx.x * 64;
    const int tid = threadIdx.x;

    for (int v = tid; v < 4096; v += 256) {
        ((float4*)W1s)[v] = ((const float4*)Wf1)[v];
        ((float4*)W2s)[v] = ((const float4*)Wf2)[v];
    }
    for (int v = tid; v < 2048; v += 256) {
        int row = v >> 5, c4 = v & 31;
        ((float4*)(As + row * Fv))[c4] = ((const float4*)(g_ln1 + (m0 + row) * Fv))[c4];
    }
    __syncthreads();

    const int ty = tid >> 4, tx = tid & 15;

    // --- GEMM 1 ---
    float acc[4][8];
    #pragma unroll
    for (int r = 0; r < 4; ++r)
        #pragma unroll
        for (int c = 0; c < 8; ++c) acc[r][c] = 0.f;

    #pragma unroll 1
    for (int k4 = 0; k4 < 32; ++k4) {
        float4 a4[4];
        #pragma unroll
        for (int r = 0; r < 4; ++r)
            a4[r] = ((const float4*)(As + (ty*4 + r) * Fv))[k4];
        #pragma unroll
        for (int kk = 0; kk < 4; ++kk) {
            const float* wrow = W1s + (k4*4 + kk) * Fv + tx*8;
            float4 b0 = *(const float4*)wrow;
            float4 b1 = *(const float4*)(wrow + 4);
            #pragma unroll
            for (int r = 0; r < 4; ++r) {
                float a = kk==0 ? a4[r].x : kk==1 ? a4[r].y : kk==2 ? a4[r].z : a4[r].w;
                acc[r][0] += a*b0.x; acc[r][1] += a*b0.y; acc[r][2] += a*b0.z; acc[r][3] += a*b0.w;
                acc[r][4] += a*b1.x; acc[r][5] += a*b1.y; acc[r][6] += a*b1.z; acc[r][7] += a*b1.w;
            }
        }
    }
    float bv1[8];
    #pragma unroll
    for (int c = 0; c < 8; ++c) bv1[c] = bf1[tx*8 + c];
    #pragma unroll
    for (int r = 0; r < 4; ++r)
        #pragma unroll
        for (int c = 0; c < 8; ++c)
            Hs[(ty*4 + r) * Fv + tx*8 + c] = fmaxf(acc[r][c] + bv1[c], 0.f);
    __syncthreads();

    // --- GEMM 2 ---
    float acc2[4][8];
    #pragma unroll
    for (int r = 0; r < 4; ++r)
        #pragma unroll
        for (int c = 0; c < 8; ++c) acc2[r][c] = 0.f;

    #pragma unroll 1
    for (int k4 = 0; k4 < 32; ++k4) {
        float4 a4[4];
        #pragma unroll
        for (int r = 0; r < 4; ++r)
            a4[r] = ((const float4*)(Hs + (ty*4 + r) * Fv))[k4];
        #pragma unroll
        for (int kk = 0; kk < 4; ++kk) {
            const float* wrow = W2s + (k4*4 + kk) * Fv + tx*8;
            float4 b0 = *(const float4*)wrow;
            float4 b1 = *(const float4*)(wrow + 4);
            #pragma unroll
            for (int r = 0; r < 4; ++r) {
                float a = kk==0 ? a4[r].x : kk==1 ? a4[r].y : kk==2 ? a4[r].z : a4[r].w;
                acc2[r][0] += a*b0.x; acc2[r][1] += a*b0.y; acc2[r][2] += a*b0.z; acc2[r][3] += a*b0.w;
                acc2[r][4] += a*b1.x; acc2[r][5] += a*b1.y; acc2[r][6] += a*b1.z; acc2[r][7] += a*b1.w;
            }
        }
    }
    float bv2[8];
    #pragma unroll
    for (int c = 0; c < 8; ++c) bv2[c] = bf2[tx*8 + c];
    __syncthreads();   // all Hs reads done before overwrite

    #pragma unroll
    for (int r = 0; r < 4; ++r) {
        int srow = ty*4 + r;
        #pragma unroll
        for (int c = 0; c < 8; ++c)
            Hs[srow * Fv + tx*8 + c] = acc2[r][c] + bv2[c] + As[srow * Fv + tx*8 + c];
    }
    __syncthreads();

    const int w = tid >> 5, lane = tid & 31;
    for (int row = w; row < 64; row += 8) {
        float4 v = ((const float4*)(Hs + row * Fv))[lane];
        float s  = v.x + v.y + v.z + v.w;
        float s2 = v.x*v.x + v.y*v.y + v.z*v.z + v.w*v.w;
        #pragma unroll
        for (int o = 16; o; o >>= 1) {
            s  += __shfl_xor_sync(0xffffffffu, s,  o);
            s2 += __shfl_xor_sync(0xffffffffu, s2, o);
        }
        float mean = s * 0.0078125f;
        float var  = s2 * 0.0078125f - mean * mean;
        float rs   = rsqrtf(var + 1e-5f);
        float4 ov = make_float4((v.x-mean)*rs, (v.y-mean)*rs, (v.z-mean)*rs, (v.w-mean)*rs);
        ((float4*)(outp + (m0 + row) * Fv))[lane] = ov;
    }
}

// =====================================================================
extern "C" void kernel_launch(void* const* d_in, const int* in_sizes, int n_in,
                              void* d_out, int out_size)
{
    const float* xl  = (const float*)d_in[0];
    const float* xh  = (const float*)d_in[1];
    const float* te  = (const float*)d_in[2];
    const float* Wq  = (const float*)d_in[3];
    const float* bq  = (const float*)d_in[4];
    const float* Wkh = (const float*)d_in[5];
    const float* bkh = (const float*)d_in[6];
    const float* Wvh = (const float*)d_in[7];
    const float* bvh = (const float*)d_in[8];
    const float* Wo  = (const float*)d_in[9];
    const float* bo  = (const float*)d_in[10];
    const float* Wf1 = (const float*)d_in[11];
    const float* bf1 = (const float*)d_in[12];
    const float* Wf2 = (const float*)d_in[13];
    const float* bf2 = (const float*)d_in[14];
    float* outp = (float*)d_out;

    const int SM_QKV  = 2 * 16384 * 4;                                 // 131072
    const int SM_ATTN = (2*128*132 + 8*8*132 + 8*8*128) * 4;           // 201728
    const int SM_PROJ = 2 * 16384 * 4;                                 // 131072
    const int SM_FFN  = (2*8192 + 2*16384) * 4;                        // 196608

    cudaFuncSetAttribute(qkv_kernel,  cudaFuncAttributeMaxDynamicSharedMemorySize, SM_QKV);
    cudaFuncSetAttribute(attn_kernel, cudaFuncAttributeMaxDynamicSharedMemorySize, SM_ATTN);
    cudaFuncSetAttribute(proj_kernel, cudaFuncAttributeMaxDynamicSharedMemorySize, SM_PROJ);
    cudaFuncSetAttribute(ffn_kernel,  cudaFuncAttributeMaxDynamicSharedMemorySize, SM_FFN);

    qkv_kernel<<<dim3(M_TOT/128, 3), 256, SM_QKV>>>(xl, xh, te, Wq, bq, Wkh, bkh, Wvh, bvh);
    attn_kernel<<<Bv*Nv, 256, SM_ATTN>>>();
    proj_kernel<<<M_TOT/128, 256, SM_PROJ>>>(xl, te, Wo, bo);
    ffn_kernel<<<M_TOT/64, 256, SM_FFN>>>(outp, Wf1, bf1, Wf2, bf2);
}

// round 4
// speedup vs baseline: 2.3764x; 2.3764x over previous
#include <cuda_runtime.h>
#include <cuda_fp16.h>
#include <math.h>

constexpr int BB = 8;
constexpr int TT = 128;
constexpr int NN = 256;
constexpr int FF = 128;
constexpr int MTOT = BB * TT * NN;   // 262144
constexpr int HP = 136;              // smem half pitch (padded)

// -------- scratch (device globals) --------
__device__ __half g_q   [MTOT * FF];
__device__ __half g_kh  [MTOT * FF];
__device__ __half g_vh  [MTOT * FF];
__device__ __half g_attn[MTOT * FF];
__device__ float  g_ln1 [MTOT * FF];

// ------------------- mma.sync helpers -------------------
__device__ __forceinline__ void ldsm4(unsigned& r0, unsigned& r1, unsigned& r2, unsigned& r3, unsigned addr) {
    asm volatile("ldmatrix.sync.aligned.m8n8.x4.shared.b16 {%0,%1,%2,%3},[%4];"
                 : "=r"(r0), "=r"(r1), "=r"(r2), "=r"(r3) : "r"(addr));
}
__device__ __forceinline__ void ldsm4t(unsigned& r0, unsigned& r1, unsigned& r2, unsigned& r3, unsigned addr) {
    asm volatile("ldmatrix.sync.aligned.m8n8.x4.trans.shared.b16 {%0,%1,%2,%3},[%4];"
                 : "=r"(r0), "=r"(r1), "=r"(r2), "=r"(r3) : "r"(addr));
}
__device__ __forceinline__ void mma16816(float* cc, const unsigned* aa, const unsigned* bb) {
    asm volatile("mma.sync.aligned.m16n8k16.row.col.f32.f16.f16.f32 "
                 "{%0,%1,%2,%3},{%4,%5,%6,%7},{%8,%9},{%0,%1,%2,%3};"
                 : "+f"(cc[0]), "+f"(cc[1]), "+f"(cc[2]), "+f"(cc[3])
                 : "r"(aa[0]), "r"(aa[1]), "r"(aa[2]), "r"(aa[3]), "r"(bb[0]), "r"(bb[1]));
}
__device__ __forceinline__ unsigned sptr(const void* ptr) {
    return (unsigned)__cvta_generic_to_shared(ptr);
}

// 128x128x128 tile GEMM: Amat [128 rows][HP] f16, Bmat [128 k][HP] f16 holding W[K][N].
// 8 warps: warp (wy,wx) computes 64x32; accumulators acc[i][j][0..3] per m16n8k16.
__device__ __forceinline__ void mma_tile(const __half* Amat, const __half* Bmat, float acc[4][4][4]) {
    const int lane = threadIdx.x & 31;
    const int warp = threadIdx.x >> 5;
    const int wy = warp >> 2;
    const int wx = warp & 3;
    const int r16 = lane & 15;
    const int hi8 = (lane >> 4) * 8;
    #pragma unroll
    for (int k0 = 0; k0 < 128; k0 += 16) {
        unsigned afrag[4][4];
        #pragma unroll
        for (int i = 0; i < 4; ++i) {
            unsigned addr = sptr(Amat + (wy * 64 + i * 16 + r16) * HP + k0 + hi8);
            ldsm4(afrag[i][0], afrag[i][1], afrag[i][2], afrag[i][3], addr);
        }
        unsigned bfrag[4][2];
        #pragma unroll
        for (int jj = 0; jj < 2; ++jj) {
            unsigned addr = sptr(Bmat + (k0 + r16) * HP + wx * 32 + jj * 16 + hi8);
            unsigned t0, t1, t2, t3;
            ldsm4t(t0, t1, t2, t3, addr);
            bfrag[jj * 2 + 0][0] = t0; bfrag[jj * 2 + 0][1] = t1;
            bfrag[jj * 2 + 1][0] = t2; bfrag[jj * 2 + 1][1] = t3;
        }
        #pragma unroll
        for (int i = 0; i < 4; ++i)
            #pragma unroll
            for (int j = 0; j < 4; ++j)
                mma16816(acc[i][j], afrag[i], bfrag[j]);
    }
}

// =====================================================================
// Kernel 1: q/kh/vh projections -> fp16 outputs.
// =====================================================================
__global__ __launch_bounds__(256) void qkv_kernel(
    const float* __restrict__ xl, const float* __restrict__ xh,
    const float* __restrict__ te,
    const float* __restrict__ Wq,  const float* __restrict__ bq,
    const float* __restrict__ Wkh, const float* __restrict__ bkh,
    const float* __restrict__ Wvh, const float* __restrict__ bvh)
{
    extern __shared__ char smraw[];
    __half* Amat = (__half*)smraw;
    __half* Bmat = Amat + 128 * HP;

    const float* Xsrc; const float* Wsrc; const float* bias;
    __half* outp; int doRelu;
    if (blockIdx.y == 0)      { Xsrc = xl; Wsrc = Wq;  bias = bq;  outp = g_q;  doRelu = 0; }
    else if (blockIdx.y == 1) { Xsrc = xh; Wsrc = Wkh; bias = bkh; outp = g_kh; doRelu = 1; }
    else                      { Xsrc = xh; Wsrc = Wvh; bias = bvh; outp = g_vh; doRelu = 1; }

    const int m0 = blockIdx.x * 128;
    const int tid = threadIdx.x;
    const float4* te4 = (const float4*)(te + (m0 / NN) * FF);
    const float4* X4 = (const float4*)Xsrc;
    const float4* W4 = (const float4*)Wsrc;

    for (int v = tid; v < 4096; v += 256) {
        int row = v >> 5;
        int c4 = v & 31;
        float4 aval = X4[(m0 + row) * 32 + c4];
        float4 tval = te4[c4];
        __half2* adst = (__half2*)(Amat + row * HP + c4 * 4);
        adst[0] = __floats2half2_rn(aval.x + tval.x, aval.y + tval.y);
        adst[1] = __floats2half2_rn(aval.z + tval.z, aval.w + tval.w);
        float4 wval = W4[v];
        __half2* wdst = (__half2*)(Bmat + row * HP + c4 * 4);
        wdst[0] = __floats2half2_rn(wval.x, wval.y);
        wdst[1] = __floats2half2_rn(wval.z, wval.w);
    }
    __syncthreads();

    float acc[4][4][4] = {};
    mma_tile(Amat, Bmat, acc);

    const int lane = tid & 31;
    const int warp = tid >> 5;
    const int wy = warp >> 2;
    const int wx = warp & 3;
    const int gid = lane >> 2;
    const int tig = lane & 3;
    #pragma unroll
    for (int i = 0; i < 4; ++i) {
        int row = m0 + wy * 64 + i * 16 + gid;
        #pragma unroll
        for (int j = 0; j < 4; ++j) {
            int col = wx * 32 + j * 8 + tig * 2;
            float2 bv = *(const float2*)(bias + col);
            float o0 = acc[i][j][0] + bv.x;
            float o1 = acc[i][j][1] + bv.y;
            float o2 = acc[i][j][2] + bv.x;
            float o3 = acc[i][j][3] + bv.y;
            if (doRelu) {
                o0 = fmaxf(o0, 0.f); o1 = fmaxf(o1, 0.f);
                o2 = fmaxf(o2, 0.f); o3 = fmaxf(o3, 0.f);
            }
            *(__half2*)(outp + row * FF + col)       = __floats2half2_rn(o0, o1);
            *(__half2*)(outp + (row + 8) * FF + col) = __floats2half2_rn(o2, o3);
        }
    }
}

// =====================================================================
// Kernel 2: per-(b,n) causal temporal attention (fp32 math, fp16 I/O).
// =====================================================================
template<int NJ>
__device__ __forceinline__ void attn_scores(const float* __restrict__ Ksm,
                                            const float* __restrict__ qw,
                                            int lane, float sc[8][4])
{
    #pragma unroll 1
    for (int k4 = 0; k4 < 32; ++k4) {
        float4 kf[NJ];
        #pragma unroll
        for (int j = 0; j < NJ; ++j)
            kf[j] = *(const float4*)(Ksm + (lane + 32 * j) * 132 + k4 * 4);
        #pragma unroll
        for (int r = 0; r < 8; ++r) {
            float4 qf = *(const float4*)(qw + r * 132 + k4 * 4);
            #pragma unroll
            for (int j = 0; j < NJ; ++j) {
                sc[r][j] += qf.x * kf[j].x;
                sc[r][j] += qf.y * kf[j].y;
                sc[r][j] += qf.z * kf[j].z;
                sc[r][j] += qf.w * kf[j].w;
            }
        }
    }
}

__global__ __launch_bounds__(256) void attn_kernel()
{
    extern __shared__ char smraw[];
    float* Ksm = (float*)smraw;            // 128*132
    float* Vsm = Ksm + 128 * 132;          // 128*132
    float* qsm = Vsm + 128 * 132;          // 8 warps * 8 rows * 132
    float* psm = qsm + 8 * 8 * 132;        // 8 warps * 8 rows * 128

    const int head = blockIdx.x;
    const int bidx = head >> 8;
    const int nidx = head & 255;
    const int base = bidx * TT * NN + nidx;

    const int tid = threadIdx.x;
    const int wrp = tid >> 5;
    const int lane = tid & 31;

    for (int s = wrp; s < TT; s += 8) {
        int off = (base + s * NN) * FF;
        __half2 kv0 = ((const __half2*)(g_kh + off))[lane * 2];
        __half2 kv1 = ((const __half2*)(g_kh + off))[lane * 2 + 1];
        __half2 vv0 = ((const __half2*)(g_vh + off))[lane * 2];
        __half2 vv1 = ((const __half2*)(g_vh + off))[lane * 2 + 1];
        float2 kf0 = __half22float2(kv0);
        float2 kf1 = __half22float2(kv1);
        float2 vf0 = __half22float2(vv0);
        float2 vf1 = __half22float2(vv1);
        ((float4*)(Ksm + s * 132))[lane] = make_float4(kf0.x, kf0.y, kf1.x, kf1.y);
        ((float4*)(Vsm + s * 132))[lane] = make_float4(vf0.x, vf0.y, vf1.x, vf1.y);
    }
    __syncthreads();

    float* qw = qsm + wrp * 8 * 132;
    float* pw = psm + wrp * 8 * 128;
    const float scale = 0.08838834764831845f;   // 1/sqrt(128)

    for (int g = 0; g < 2; ++g) {
        const int tbase = wrp * 16 + g * 8;

        #pragma unroll
        for (int r = 0; r < 8; ++r) {
            int off = (base + (tbase + r) * NN) * FF;
            __half2 qv0 = ((const __half2*)(g_q + off))[lane * 2];
            __half2 qv1 = ((const __half2*)(g_q + off))[lane * 2 + 1];
            float2 qf0 = __half22float2(qv0);
            float2 qf1 = __half22float2(qv1);
            ((float4*)(qw + r * 132))[lane] = make_float4(qf0.x, qf0.y, qf1.x, qf1.y);
        }
        __syncwarp();

        float sc[8][4];
        #pragma unroll
        for (int r = 0; r < 8; ++r) { sc[r][0] = 0.f; sc[r][1] = 0.f; sc[r][2] = 0.f; sc[r][3] = 0.f; }

        const int njv = (tbase + 39) >> 5;   // causal: j blocks with lane+32j possibly <= t
        switch (njv) {
            case 1:  attn_scores<1>(Ksm, qw, lane, sc); break;
            case 2:  attn_scores<2>(Ksm, qw, lane, sc); break;
            case 3:  attn_scores<3>(Ksm, qw, lane, sc); break;
            default: attn_scores<4>(Ksm, qw, lane, sc); break;
        }

        #pragma unroll
        for (int r = 0; r < 8; ++r) {
            const int trow = tbase + r;
            float mx = -1e30f;
            #pragma unroll
            for (int j = 0; j < 4; ++j) {
                int scol = lane + 32 * j;
                float v = (scol <= trow) ? sc[r][j] * scale : -1e30f;
                sc[r][j] = v;
                mx = fmaxf(mx, v);
            }
            #pragma unroll
            for (int o = 16; o; o >>= 1) mx = fmaxf(mx, __shfl_xor_sync(0xffffffffu, mx, o));
            float ssum = 0.f;
            #pragma unroll
            for (int j = 0; j < 4; ++j) {
                float e = __expf(sc[r][j] - mx);
                sc[r][j] = e;
                ssum += e;
            }
            #pragma unroll
            for (int o = 16; o; o >>= 1) ssum += __shfl_xor_sync(0xffffffffu, ssum, o);
            float inv = 1.f / ssum;
            #pragma unroll
            for (int j = 0; j < 4; ++j) pw[r * 128 + lane + 32 * j] = sc[r][j] * inv;
        }
        __syncwarp();

        float4 ov[8];
        #pragma unroll
        for (int r = 0; r < 8; ++r) ov[r] = make_float4(0.f, 0.f, 0.f, 0.f);
        const int smax = tbase + 8;               // causal: p==0 beyond this
        for (int s = 0; s < smax; ++s) {
            float4 vval = *(const float4*)(Vsm + s * 132 + 4 * lane);
            #pragma unroll
            for (int r = 0; r < 8; ++r) {
                float p = pw[r * 128 + s];
                ov[r].x += p * vval.x;
                ov[r].y += p * vval.y;
                ov[r].z += p * vval.z;
                ov[r].w += p * vval.w;
            }
        }
        #pragma unroll
        for (int r = 0; r < 8; ++r) {
            int off = (base + (tbase + r) * NN) * FF;
            ((__half2*)(g_attn + off))[lane * 2]     = __floats2half2_rn(ov[r].x, ov[r].y);
            ((__half2*)(g_attn + off))[lane * 2 + 1] = __floats2half2_rn(ov[r].z, ov[r].w);
        }
        __syncwarp();
    }
}

// =====================================================================
// Kernel 3: val = attn @ Wo + bo + (xl + te); g_ln1 = LayerNorm(val) fp32
// =====================================================================
__global__ __launch_bounds__(256) void proj_kernel(
    const float* __restrict__ xl, const float* __restrict__ te,
    const float* __restrict__ Wo, const float* __restrict__ bo)
{
    extern __shared__ char smraw[];
    __half* Amat = (__half*)smraw;
    __half* Bmat = Amat + 128 * HP;
    float*  Cmat = (float*)smraw;      // overlay after mma (67584 <= 69632 bytes)

    const int m0 = blockIdx.x * 128;
    const int tid = threadIdx.x;

    for (int v = tid; v < 2048; v += 256) {           // direct f16 copy of attn tile
        int row = v >> 4;
        int q16 = v & 15;
        ((uint4*)(Amat + row * HP))[q16] = ((const uint4*)(g_attn + (m0 + row) * FF))[q16];
    }
    const float4* W4 = (const float4*)Wo;
    for (int v = tid; v < 4096; v += 256) {
        int row = v >> 5;
        int c4 = v & 31;
        float4 wval = W4[v];
        __half2* wdst = (__half2*)(Bmat + row * HP + c4 * 4);
        wdst[0] = __floats2half2_rn(wval.x, wval.y);
        wdst[1] = __floats2half2_rn(wval.z, wval.w);
    }
    __syncthreads();

    float acc[4][4][4] = {};
    mma_tile(Amat, Bmat, acc);
    __syncthreads();                   // all smem reads done; Cmat overlays Amat/Bmat

    const float4* xl4 = (const float4*)xl;
    const float4* te4 = (const float4*)(te + (m0 / NN) * FF);
    for (int v = tid; v < 4096; v += 256) {
        int row = v >> 5;
        int c4 = v & 31;
        float4 aval = xl4[(m0 + row) * 32 + c4];
        float4 tval = te4[c4];
        ((float4*)(Cmat + row * 132))[c4] =
            make_float4(aval.x + tval.x, aval.y + tval.y, aval.z + tval.z, aval.w + tval.w);
    }
    __syncthreads();

    const int lane = tid & 31;
    const int warp = tid >> 5;
    const int wy = warp >> 2;
    const int wx = warp & 3;
    const int gid = lane >> 2;
    const int tig = lane & 3;
    #pragma unroll
    for (int i = 0; i < 4; ++i) {
        int row = wy * 64 + i * 16 + gid;
        #pragma unroll
        for (int j = 0; j < 4; ++j) {
            int col = wx * 32 + j * 8 + tig * 2;
            float2 bv = *(const float2*)(bo + col);
            Cmat[row * 132 + col]           += acc[i][j][0] + bv.x;
            Cmat[row * 132 + col + 1]       += acc[i][j][1] + bv.y;
            Cmat[(row + 8) * 132 + col]     += acc[i][j][2] + bv.x;
            Cmat[(row + 8) * 132 + col + 1] += acc[i][j][3] + bv.y;
        }
    }
    __syncthreads();

    for (int row = warp; row < 128; row += 8) {
        float4 vval = ((const float4*)(Cmat + row * 132))[lane];
        float s1 = vval.x + vval.y + vval.z + vval.w;
        float s2 = vval.x * vval.x + vval.y * vval.y + vval.z * vval.z + vval.w * vval.w;
        #pragma unroll
        for (int o = 16; o; o >>= 1) {
            s1 += __shfl_xor_sync(0xffffffffu, s1, o);
            s2 += __shfl_xor_sync(0xffffffffu, s2, o);
        }
        float mean = s1 * 0.0078125f;
        float var = s2 * 0.0078125f - mean * mean;
        float rsd = rsqrtf(var + 1e-5f);
        ((float4*)(g_ln1 + (m0 + row) * FF))[lane] =
            make_float4((vval.x - mean) * rsd, (vval.y - mean) * rsd,
                        (vval.z - mean) * rsd, (vval.w - mean) * rsd);
    }
}

// =====================================================================
// Kernel 4: h = relu(ln1@Wf1+bf1); h2 = h@Wf2+bf2; out = LN(h2 + ln1)
// =====================================================================
__global__ __launch_bounds__(256) void ffn_kernel(
    float* __restrict__ outp,
    const float* __restrict__ Wf1, const float* __restrict__ bf1,
    const float* __restrict__ Wf2, const float* __restrict__ bf2)
{
    extern __shared__ char smraw[];
    __half* Amat = (__half*)smraw;              // ln1 f16, then H f16
    __half* W1m = Amat + 128 * HP;
    __half* W2m = Amat + 2 * 128 * HP;
    float*  Cmat = (float*)(Amat + 3 * 128 * HP);   // residual + final staging

    const int m0 = blockIdx.x * 128;
    const int tid = threadIdx.x;
    const float4* ln4 = (const float4*)g_ln1;
    const float4* wf14 = (const float4*)Wf1;
    const float4* wf24 = (const float4*)Wf2;

    for (int v = tid; v < 4096; v += 256) {
        int row = v >> 5;
        int c4 = v & 31;
        float4 aval = ln4[(m0 + row) * 32 + c4];
        ((float4*)(Cmat + row * 132))[c4] = aval;
        __half2* adst = (__half2*)(Amat + row * HP + c4 * 4);
        adst[0] = __floats2half2_rn(aval.x, aval.y);
        adst[1] = __floats2half2_rn(aval.z, aval.w);
        float4 wv1 = wf14[v];
        __half2* wdst1 = (__half2*)(W1m + row * HP + c4 * 4);
        wdst1[0] = __floats2half2_rn(wv1.x, wv1.y);
        wdst1[1] = __floats2half2_rn(wv1.z, wv1.w);
        float4 wv2 = wf24[v];
        __half2* wdst2 = (__half2*)(W2m + row * HP + c4 * 4);
        wdst2[0] = __floats2half2_rn(wv2.x, wv2.y);
        wdst2[1] = __floats2half2_rn(wv2.z, wv2.w);
    }
    __syncthreads();

    float acc[4][4][4] = {};
    mma_tile(Amat, W1m, acc);
    __syncthreads();                   // done reading Amat before overwriting with H

    const int lane = tid & 31;
    const int warp = tid >> 5;
    const int wy = warp >> 2;
    const int wx = warp & 3;
    const int gid = lane >> 2;
    const int tig = lane & 3;
    #pragma unroll
    for (int i = 0; i < 4; ++i) {
        int row = wy * 64 + i * 16 + gid;
        #pragma unroll
        for (int j = 0; j < 4; ++j) {
            int col = wx * 32 + j * 8 + tig * 2;
            float2 bv = *(const float2*)(bf1 + col);
            *(__half2*)(Amat + row * HP + col) =
                __floats2half2_rn(fmaxf(acc[i][j][0] + bv.x, 0.f), fmaxf(acc[i][j][1] + bv.y, 0.f));
            *(__half2*)(Amat + (row + 8) * HP + col) =
                __floats2half2_rn(fmaxf(acc[i][j][2] + bv.x, 0.f), fmaxf(acc[i][j][3] + bv.y, 0.f));
        }
    }
    __syncthreads();

    float acc2[4][4][4] = {};
    mma_tile(Amat, W2m, acc2);

    #pragma unroll
    for (int i = 0; i < 4; ++i) {
        int row = wy * 64 + i * 16 + gid;
        #pragma unroll
        for (int j = 0; j < 4; ++j) {
            int col = wx * 32 + j * 8 + tig * 2;
            float2 bv = *(const float2*)(bf2 + col);
            Cmat[row * 132 + col]           += acc2[i][j][0] + bv.x;
            Cmat[row * 132 + col + 1]       += acc2[i][j][1] + bv.y;
            Cmat[(row + 8) * 132 + col]     += acc2[i][j][2] + bv.x;
            Cmat[(row + 8) * 132 + col + 1] += acc2[i][j][3] + bv.y;
        }
    }
    __syncthreads();

    for (int row = warp; row < 128; row += 8) {
        float4 vval = ((const float4*)(Cmat + row * 132))[lane];
        float s1 = vval.x + vval.y + vval.z + vval.w;
        float s2 = vval.x * vval.x + vval.y * vval.y + vval.z * vval.z + vval.w * vval.w;
        #pragma unroll
        for (int o = 16; o; o >>= 1) {
            s1 += __shfl_xor_sync(0xffffffffu, s1, o);
            s2 += __shfl_xor_sync(0xffffffffu, s2, o);
        }
        float mean = s1 * 0.0078125f;
        float var = s2 * 0.0078125f - mean * mean;
        float rsd = rsqrtf(var + 1e-5f);
        ((float4*)(outp + (m0 + row) * FF))[lane] =
            make_float4((vval.x - mean) * rsd, (vval.y - mean) * rsd,
                        (vval.z - mean) * rsd, (vval.w - mean) * rsd);
    }
}

// =====================================================================
extern "C" void kernel_launch(void* const* d_in, const int* in_sizes, int n_in,
                              void* d_out, int out_size)
{
    const float* xl  = (const float*)d_in[0];
    const float* xh  = (const float*)d_in[1];
    const float* te  = (const float*)d_in[2];
    const float* Wq  = (const float*)d_in[3];
    const float* bq  = (const float*)d_in[4];
    const float* Wkh = (const float*)d_in[5];
    const float* bkh = (const float*)d_in[6];
    const float* Wvh = (const float*)d_in[7];
    const float* bvh = (const float*)d_in[8];
    const float* Wo  = (const float*)d_in[9];
    const float* bo  = (const float*)d_in[10];
    const float* Wf1 = (const float*)d_in[11];
    const float* bf1 = (const float*)d_in[12];
    const float* Wf2 = (const float*)d_in[13];
    const float* bf2 = (const float*)d_in[14];
    float* outp = (float*)d_out;

    const int smQkv  = 2 * 128 * HP * 2;                          // 69632
    const int smAttn = (2 * 128 * 132 + 8 * 8 * 132 + 8 * 8 * 128) * 4;  // 201728
    const int smProj = 2 * 128 * HP * 2;                          // 69632
    const int smFfn  = 3 * 128 * HP * 2 + 128 * 132 * 4;          // 172032

    cudaFuncSetAttribute(qkv_kernel,  cudaFuncAttributeMaxDynamicSharedMemorySize, smQkv);
    cudaFuncSetAttribute(attn_kernel, cudaFuncAttributeMaxDynamicSharedMemorySize, smAttn);
    cudaFuncSetAttribute(proj_kernel, cudaFuncAttributeMaxDynamicSharedMemorySize, smProj);
    cudaFuncSetAttribute(ffn_kernel,  cudaFuncAttributeMaxDynamicSharedMemorySize, smFfn);

    qkv_kernel<<<dim3(MTOT / 128, 3), 256, smQkv>>>(xl, xh, te, Wq, bq, Wkh, bkh, Wvh, bvh);
    attn_kernel<<<BB * NN, 256, smAttn>>>();
    proj_kernel<<<MTOT / 128, 256, smProj>>>(xl, te, Wo, bo);
    ffn_kernel<<<MTOT / 128, 256, smFfn>>>(outp, Wf1, bf1, Wf2, bf2);
}

// round 5
// speedup vs baseline: 3.7786x; 1.5901x over previous
#include <cuda_runtime.h>
#include <cuda_fp16.h>
#include <math.h>

constexpr int BB = 8;
constexpr int TT = 128;
constexpr int NN = 256;
constexpr int FF = 128;
constexpr int MTOT = BB * TT * NN;   // 262144
constexpr int HP = 136;              // smem half pitch (padded)

// -------- scratch (device globals) --------
__device__ __half g_q   [MTOT * FF];
__device__ __half g_kh  [MTOT * FF];
__device__ __half g_vh  [MTOT * FF];
__device__ __half g_attn[MTOT * FF];

// ------------------- mma.sync helpers -------------------
__device__ __forceinline__ void ldsm4(unsigned& r0, unsigned& r1, unsigned& r2, unsigned& r3, unsigned addr) {
    asm volatile("ldmatrix.sync.aligned.m8n8.x4.shared.b16 {%0,%1,%2,%3},[%4];"
                 : "=r"(r0), "=r"(r1), "=r"(r2), "=r"(r3) : "r"(addr));
}
__device__ __forceinline__ void ldsm4t(unsigned& r0, unsigned& r1, unsigned& r2, unsigned& r3, unsigned addr) {
    asm volatile("ldmatrix.sync.aligned.m8n8.x4.trans.shared.b16 {%0,%1,%2,%3},[%4];"
                 : "=r"(r0), "=r"(r1), "=r"(r2), "=r"(r3) : "r"(addr));
}
__device__ __forceinline__ void mma16816(float* cc, const unsigned* aa, const unsigned* bb) {
    asm volatile("mma.sync.aligned.m16n8k16.row.col.f32.f16.f16.f32 "
                 "{%0,%1,%2,%3},{%4,%5,%6,%7},{%8,%9},{%0,%1,%2,%3};"
                 : "+f"(cc[0]), "+f"(cc[1]), "+f"(cc[2]), "+f"(cc[3])
                 : "r"(aa[0]), "r"(aa[1]), "r"(aa[2]), "r"(aa[3]), "r"(bb[0]), "r"(bb[1]));
}
__device__ __forceinline__ unsigned sptr(const void* ptr) {
    return (unsigned)__cvta_generic_to_shared(ptr);
}
__device__ __forceinline__ unsigned pack2(float a, float b) {
    __half2 h = __floats2half2_rn(a, b);
    return *reinterpret_cast<unsigned*>(&h);
}

// 128x128x128 tile GEMM: Amat [128 rows][HP] f16, Bmat [128 k][HP] f16 holding W[K][N].
// 8 warps: warp (wy,wx) computes 64x32.
__device__ __forceinline__ void mma_tile(const __half* Amat, const __half* Bmat, float acc[4][4][4]) {
    const int lane = threadIdx.x & 31;
    const int warp = threadIdx.x >> 5;
    const int wy = warp >> 2;
    const int wx = warp & 3;
    const int r16 = lane & 15;
    const int hi8 = (lane >> 4) * 8;
    #pragma unroll
    for (int k0 = 0; k0 < 128; k0 += 16) {
        unsigned afrag[4][4];
        #pragma unroll
        for (int i = 0; i < 4; ++i) {
            unsigned addr = sptr(Amat + (wy * 64 + i * 16 + r16) * HP + k0 + hi8);
            ldsm4(afrag[i][0], afrag[i][1], afrag[i][2], afrag[i][3], addr);
        }
        unsigned bfrag[4][2];
        #pragma unroll
        for (int jj = 0; jj < 2; ++jj) {
            unsigned addr = sptr(Bmat + (k0 + r16) * HP + wx * 32 + jj * 16 + hi8);
            unsigned t0, t1, t2, t3;
            ldsm4t(t0, t1, t2, t3, addr);
            bfrag[jj * 2 + 0][0] = t0; bfrag[jj * 2 + 0][1] = t1;
            bfrag[jj * 2 + 1][0] = t2; bfrag[jj * 2 + 1][1] = t3;
        }
        #pragma unroll
        for (int i = 0; i < 4; ++i)
            #pragma unroll
            for (int j = 0; j < 4; ++j)
                mma16816(acc[i][j], afrag[i], bfrag[j]);
    }
}

// =====================================================================
// Kernel 1: q/kh/vh projections -> fp16 outputs.
// =====================================================================
__global__ __launch_bounds__(256) void qkv_kernel(
    const float* __restrict__ xl, const float* __restrict__ xh,
    const float* __restrict__ te,
    const float* __restrict__ Wq,  const float* __restrict__ bq,
    const float* __restrict__ Wkh, const float* __restrict__ bkh,
    const float* __restrict__ Wvh, const float* __restrict__ bvh)
{
    extern __shared__ char smraw[];
    __half* Amat = (__half*)smraw;
    __half* Bmat = Amat + 128 * HP;

    const float* Xsrc; const float* Wsrc; const float* bias;
    __half* outp; int doRelu;
    if (blockIdx.y == 0)      { Xsrc = xl; Wsrc = Wq;  bias = bq;  outp = g_q;  doRelu = 0; }
    else if (blockIdx.y == 1) { Xsrc = xh; Wsrc = Wkh; bias = bkh; outp = g_kh; doRelu = 1; }
    else                      { Xsrc = xh; Wsrc = Wvh; bias = bvh; outp = g_vh; doRelu = 1; }

    const int m0 = blockIdx.x * 128;
    const int tid = threadIdx.x;
    const float4* te4 = (const float4*)(te + (m0 / NN) * FF);
    const float4* X4 = (const float4*)Xsrc;
    const float4* W4 = (const float4*)Wsrc;

    for (int v = tid; v < 4096; v += 256) {
        int row = v >> 5;
        int c4 = v & 31;
        float4 aval = X4[(m0 + row) * 32 + c4];
        float4 tval = te4[c4];
        __half2* adst = (__half2*)(Amat + row * HP + c4 * 4);
        adst[0] = __floats2half2_rn(aval.x + tval.x, aval.y + tval.y);
        adst[1] = __floats2half2_rn(aval.z + tval.z, aval.w + tval.w);
        float4 wval = W4[v];
        __half2* wdst = (__half2*)(Bmat + row * HP + c4 * 4);
        wdst[0] = __floats2half2_rn(wval.x, wval.y);
        wdst[1] = __floats2half2_rn(wval.z, wval.w);
    }
    __syncthreads();

    float acc[4][4][4] = {};
    mma_tile(Amat, Bmat, acc);

    const int lane = tid & 31;
    const int warp = tid >> 5;
    const int wy = warp >> 2;
    const int wx = warp & 3;
    const int gid = lane >> 2;
    const int tig = lane & 3;
    #pragma unroll
    for (int i = 0; i < 4; ++i) {
        int row = m0 + wy * 64 + i * 16 + gid;
        #pragma unroll
        for (int j = 0; j < 4; ++j) {
            int col = wx * 32 + j * 8 + tig * 2;
            float2 bv = *(const float2*)(bias + col);
            float o0 = acc[i][j][0] + bv.x;
            float o1 = acc[i][j][1] + bv.y;
            float o2 = acc[i][j][2] + bv.x;
            float o3 = acc[i][j][3] + bv.y;
            if (doRelu) {
                o0 = fmaxf(o0, 0.f); o1 = fmaxf(o1, 0.f);
                o2 = fmaxf(o2, 0.f); o3 = fmaxf(o3, 0.f);
            }
            *(__half2*)(outp + row * FF + col)       = __floats2half2_rn(o0, o1);
            *(__half2*)(outp + (row + 8) * FF + col) = __floats2half2_rn(o2, o3);
        }
    }
}

// =====================================================================
// Kernel 2: per-(b,n) causal temporal attention, tensor-core version.
// Warp w owns rows t in [16w, 16w+16); computes s-tile-pairs jp <= w.
// =====================================================================
template<int NP>
__device__ __forceinline__ void attn_warp(const __half* Qs, const __half* Ks, const __half* Vs,
                                          int base, int w, int lane)
{
    const int r16 = lane & 15;
    const int hi8 = (lane >> 4) * 8;
    const int gid = lane >> 2;
    const int tig = lane & 3;

    // A fragments of Q for rows 16w..16w+15, all 8 k-steps.
    unsigned aq[8][4];
    #pragma unroll
    for (int k = 0; k < 8; ++k) {
        unsigned addr = sptr(Qs + (16 * w + r16) * HP + k * 16 + hi8);
        ldsm4(aq[k][0], aq[k][1], aq[k][2], aq[k][3], addr);
    }

    // S = Q K^T for s-tiles 0..2*NP-1 (s < 16*NP).
    float c[2 * NP][4];
    #pragma unroll
    for (int js = 0; js < 2 * NP; ++js) {
        c[js][0] = 0.f; c[js][1] = 0.f; c[js][2] = 0.f; c[js][3] = 0.f;
    }
    #pragma unroll
    for (int jp = 0; jp < NP; ++jp) {
        #pragma unroll
        for (int k = 0; k < 8; ++k) {
            unsigned t0, t1, t2, t3;
            unsigned addr = sptr(Ks + (16 * jp + r16) * HP + k * 16 + hi8);
            ldsm4(t0, t1, t2, t3, addr);
            unsigned bE[2] = { t0, t2 };
            unsigned bO[2] = { t1, t3 };
            mma16816(c[2 * jp],     aq[k], bE);
            mma16816(c[2 * jp + 1], aq[k], bO);
        }
    }

    // softmax (fp32, registers). rows: tlo = 16w+gid (c[..][0,1]), thi = tlo+8 (c[..][2,3])
    const float scale = 0.08838834764831845f;   // 1/sqrt(128)
    const int tlo = 16 * w + gid;
    const int thi = tlo + 8;
    float mlo = -1e30f, mhi = -1e30f;
    #pragma unroll
    for (int js = 0; js < 2 * NP; ++js) {
        int s0 = 8 * js + 2 * tig;
        int s1 = s0 + 1;
        c[js][0] *= scale; c[js][1] *= scale;
        c[js][2] *= scale; c[js][3] *= scale;
        if (js >= 2 * NP - 2) {          // diagonal block: apply causal mask
            if (s0 > tlo) c[js][0] = -1e30f;
            if (s1 > tlo) c[js][1] = -1e30f;
            if (s0 > thi) c[js][2] = -1e30f;
            if (s1 > thi) c[js][3] = -1e30f;
        }
        mlo = fmaxf(mlo, fmaxf(c[js][0], c[js][1]));
        mhi = fmaxf(mhi, fmaxf(c[js][2], c[js][3]));
    }
    #pragma unroll
    for (int o = 1; o <= 2; o <<= 1) {
        mlo = fmaxf(mlo, __shfl_xor_sync(0xffffffffu, mlo, o));
        mhi = fmaxf(mhi, __shfl_xor_sync(0xffffffffu, mhi, o));
    }
    float slo = 0.f, shi = 0.f;
    #pragma unroll
    for (int js = 0; js < 2 * NP; ++js) {
        c[js][0] = __expf(c[js][0] - mlo);
        c[js][1] = __expf(c[js][1] - mlo);
        c[js][2] = __expf(c[js][2] - mhi);
        c[js][3] = __expf(c[js][3] - mhi);
        slo += c[js][0] + c[js][1];
        shi += c[js][2] + c[js][3];
    }
    #pragma unroll
    for (int o = 1; o <= 2; o <<= 1) {
        slo += __shfl_xor_sync(0xffffffffu, slo, o);
        shi += __shfl_xor_sync(0xffffffffu, shi, o);
    }
    const float invlo = 1.f / slo;
    const float invhi = 1.f / shi;

    // O = P V (P unnormalized fp16; normalize at the end).
    float ov[16][4];
    #pragma unroll
    for (int jt = 0; jt < 16; ++jt) {
        ov[jt][0] = 0.f; ov[jt][1] = 0.f; ov[jt][2] = 0.f; ov[jt][3] = 0.f;
    }
    #pragma unroll
    for (int ks = 0; ks < NP; ++ks) {
        unsigned ap[4];
        ap[0] = pack2(c[2 * ks][0],     c[2 * ks][1]);
        ap[1] = pack2(c[2 * ks][2],     c[2 * ks][3]);
        ap[2] = pack2(c[2 * ks + 1][0], c[2 * ks + 1][1]);
        ap[3] = pack2(c[2 * ks + 1][2], c[2 * ks + 1][3]);
        #pragma unroll
        for (int jf = 0; jf < 8; ++jf) {
            unsigned t0, t1, t2, t3;
            unsigned addr = sptr(Vs + (16 * ks + r16) * HP + jf * 16 + hi8);
            ldsm4t(t0, t1, t2, t3, addr);
            unsigned b0[2] = { t0, t1 };
            unsigned b1[2] = { t2, t3 };
            mma16816(ov[2 * jf],     ap, b0);
            mma16816(ov[2 * jf + 1], ap, b1);
        }
    }

    // write output fp16
    __half* olo = g_attn + (base + tlo * NN) * FF;
    __half* ohi = g_attn + (base + thi * NN) * FF;
    #pragma unroll
    for (int jt = 0; jt < 16; ++jt) {
        int col = jt * 8 + tig * 2;
        *(__half2*)(olo + col) = __floats2half2_rn(ov[jt][0] * invlo, ov[jt][1] * invlo);
        *(__half2*)(ohi + col) = __floats2half2_rn(ov[jt][2] * invhi, ov[jt][3] * invhi);
    }
}

__global__ __launch_bounds__(256) void attn_kernel()
{
    extern __shared__ char smraw[];
    __half* Qs = (__half*)smraw;           // 128*HP halves
    __half* Ks = Qs + 128 * HP;
    __half* Vs = Ks + 128 * HP;

    const int head = blockIdx.x;
    const int bidx = head >> 8;
    const int nidx = head & 255;
    const int base = bidx * TT * NN + nidx;

    const int tid = threadIdx.x;
    const int w = tid >> 5;
    const int lane = tid & 31;

    for (int v = tid; v < 2048; v += 256) {
        int row = v >> 4;
        int q16 = v & 15;
        int off = (base + row * NN) * FF;
        ((uint4*)(Qs + row * HP))[q16] = ((const uint4*)(g_q + off))[q16];
        ((uint4*)(Ks + row * HP))[q16] = ((const uint4*)(g_kh + off))[q16];
        ((uint4*)(Vs + row * HP))[q16] = ((const uint4*)(g_vh + off))[q16];
    }
    __syncthreads();

    switch (w) {
        case 0: attn_warp<1>(Qs, Ks, Vs, base, 0, lane); break;
        case 1: attn_warp<2>(Qs, Ks, Vs, base, 1, lane); break;
        case 2: attn_warp<3>(Qs, Ks, Vs, base, 2, lane); break;
        case 3: attn_warp<4>(Qs, Ks, Vs, base, 3, lane); break;
        case 4: attn_warp<5>(Qs, Ks, Vs, base, 4, lane); break;
        case 5: attn_warp<6>(Qs, Ks, Vs, base, 5, lane); break;
        case 6: attn_warp<7>(Qs, Ks, Vs, base, 6, lane); break;
        default: attn_warp<8>(Qs, Ks, Vs, base, 7, lane); break;
    }
}

// =====================================================================
// Kernel 3 (fused proj+ffn):
//   val = attn@Wo + bo + (xl+te); ln1 = LN(val)
//   h = relu(ln1@Wf1+bf1); h2 = h@Wf2+bf2; out = LN(h2 + ln1)
// =====================================================================
__global__ __launch_bounds__(256) void tail_kernel(
    float* __restrict__ outp,
    const float* __restrict__ xl, const float* __restrict__ te,
    const float* __restrict__ Wo, const float* __restrict__ bo,
    const float* __restrict__ Wf1, const float* __restrict__ bf1,
    const float* __restrict__ Wf2, const float* __restrict__ bf2)
{
    extern __shared__ char smraw[];
    __half* Amat = (__half*)smraw;              // data tile (attn -> ln1 -> h)
    __half* W0m = Amat + 128 * HP;
    __half* W1m = Amat + 2 * 128 * HP;
    __half* W2m = Amat + 3 * 128 * HP;
    float*  Cmat = (float*)(Amat + 4 * 128 * HP);   // fp32 residual / staging [128][132]

    const int m0 = blockIdx.x * 128;
    const int tid = threadIdx.x;

    for (int v = tid; v < 2048; v += 256) {           // attn tile: direct f16 copy
        int row = v >> 4;
        int q16 = v & 15;
        ((uint4*)(Amat + row * HP))[q16] = ((const uint4*)(g_attn + (m0 + row) * FF))[q16];
    }
    const float4* wo4 = (const float4*)Wo;
    const float4* wf14 = (const float4*)Wf1;
    const float4* wf24 = (const float4*)Wf2;
    const float4* xl4 = (const float4*)xl;
    const float4* te4 = (const float4*)(te + (m0 / NN) * FF);
    for (int v = tid; v < 4096; v += 256) {
        int row = v >> 5;
        int c4 = v & 31;
        float4 w0 = wo4[v];
        __half2* d0 = (__half2*)(W0m + row * HP + c4 * 4);
        d0[0] = __floats2half2_rn(w0.x, w0.y);
        d0[1] = __floats2half2_rn(w0.z, w0.w);
        float4 w1 = wf14[v];
        __half2* d1 = (__half2*)(W1m + row * HP + c4 * 4);
        d1[0] = __floats2half2_rn(w1.x, w1.y);
        d1[1] = __floats2half2_rn(w1.z, w1.w);
        float4 w2 = wf24[v];
        __half2* d2 = (__half2*)(W2m + row * HP + c4 * 4);
        d2[0] = __floats2half2_rn(w2.x, w2.y);
        d2[1] = __floats2half2_rn(w2.z, w2.w);
        float4 aval = xl4[(m0 + row) * 32 + c4];
        float4 tval = te4[c4];
        ((float4*)(Cmat + row * 132))[c4] =
            make_float4(aval.x + tval.x, aval.y + tval.y, aval.z + tval.z, aval.w + tval.w);
    }
    __syncthreads();

    const int lane = tid & 31;
    const int warp = tid >> 5;
    const int wy = warp >> 2;
    const int wx = warp & 3;
    const int gid = lane >> 2;
    const int tig = lane & 3;

    // ---- proj GEMM ----
    float acc[4][4][4] = {};
    mma_tile(Amat, W0m, acc);
    __syncthreads();   // Amat reads done

    #pragma unroll
    for (int i = 0; i < 4; ++i) {
        int row = wy * 64 + i * 16 + gid;
        #pragma unroll
        for (int j = 0; j < 4; ++j) {
            int col = wx * 32 + j * 8 + tig * 2;
            float2 bv = *(const float2*)(bo + col);
            Cmat[row * 132 + col]           += acc[i][j][0] + bv.x;
            Cmat[row * 132 + col + 1]       += acc[i][j][1] + bv.y;
            Cmat[(row + 8) * 132 + col]     += acc[i][j][2] + bv.x;
            Cmat[(row + 8) * 132 + col + 1] += acc[i][j][3] + bv.y;
        }
    }
    __syncthreads();

    // ---- LayerNorm 1: Cmat -> normalized fp32 (Cmat) + fp16 (Amat) ----
    for (int row = warp; row < 128; row += 8) {
        float4 vval = ((const float4*)(Cmat + row * 132))[lane];
        float s1 = vval.x + vval.y + vval.z + vval.w;
        float s2 = vval.x * vval.x + vval.y * vval.y + vval.z * vval.z + vval.w * vval.w;
        #pragma unroll
        for (int o = 16; o; o >>= 1) {
            s1 += __shfl_xor_sync(0xffffffffu, s1, o);
            s2 += __shfl_xor_sync(0xffffffffu, s2, o);
        }
        float mean = s1 * 0.0078125f;
        float var = s2 * 0.0078125f - mean * mean;
        float rsd = rsqrtf(var + 1e-5f);
        float n0 = (vval.x - mean) * rsd;
        float n1 = (vval.y - mean) * rsd;
        float n2 = (vval.z - mean) * rsd;
        float n3 = (vval.w - mean) * rsd;
        ((float4*)(Cmat + row * 132))[lane] = make_float4(n0, n1, n2, n3);
        __half2* adst = (__half2*)(Amat + row * HP + lane * 4);
        adst[0] = __floats2half2_rn(n0, n1);
        adst[1] = __floats2half2_rn(n2, n3);
    }
    __syncthreads();

    // ---- FFN GEMM 1 ----
    float acc2[4][4][4] = {};
    mma_tile(Amat, W1m, acc2);
    __syncthreads();   // Amat reads done before overwrite with H

    #pragma unroll
    for (int i = 0; i < 4; ++i) {
        int row = wy * 64 + i * 16 + gid;
        #pragma unroll
        for (int j = 0; j < 4; ++j) {
            int col = wx * 32 + j * 8 + tig * 2;
            float2 bv = *(const float2*)(bf1 + col);
            *(__half2*)(Amat + row * HP + col) =
                __floats2half2_rn(fmaxf(acc2[i][j][0] + bv.x, 0.f), fmaxf(acc2[i][j][1] + bv.y, 0.f));
            *(__half2*)(Amat + (row + 8) * HP + col) =
                __floats2half2_rn(fmaxf(acc2[i][j][2] + bv.x, 0.f), fmaxf(acc2[i][j][3] + bv.y, 0.f));
        }
    }
    __syncthreads();

    // ---- FFN GEMM 2 ----
    float acc3[4][4][4] = {};
    mma_tile(Amat, W2m, acc3);

    #pragma unroll
    for (int i = 0; i < 4; ++i) {
        int row = wy * 64 + i * 16 + gid;
        #pragma unroll
        for (int j = 0; j < 4; ++j) {
            int col = wx * 32 + j * 8 + tig * 2;
            float2 bv = *(const float2*)(bf2 + col);
            Cmat[row * 132 + col]           += acc3[i][j][0] + bv.x;
            Cmat[row * 132 + col + 1]       += acc3[i][j][1] + bv.y;
            Cmat[(row + 8) * 132 + col]     += acc3[i][j][2] + bv.x;
            Cmat[(row + 8) * 132 + col + 1] += acc3[i][j][3] + bv.y;
        }
    }
    __syncthreads();

    // ---- LayerNorm 2 -> output ----
    for (int row = warp; row < 128; row += 8) {
        float4 vval = ((const float4*)(Cmat + row * 132))[lane];
        float s1 = vval.x + vval.y + vval.z + vval.w;
        float s2 = vval.x * vval.x + vval.y * vval.y + vval.z * vval.z + vval.w * vval.w;
        #pragma unroll
        for (int o = 16; o; o >>= 1) {
            s1 += __shfl_xor_sync(0xffffffffu, s1, o);
            s2 += __shfl_xor_sync(0xffffffffu, s2, o);
        }
        float mean = s1 * 0.0078125f;
        float var = s2 * 0.0078125f - mean * mean;
        float rsd = rsqrtf(var + 1e-5f);
        ((float4*)(outp + (m0 + row) * FF))[lane] =
            make_float4((vval.x - mean) * rsd, (vval.y - mean) * rsd,
                        (vval.z - mean) * rsd, (vval.w - mean) * rsd);
    }
}

// =====================================================================
extern "C" void kernel_launch(void* const* d_in, const int* in_sizes, int n_in,
                              void* d_out, int out_size)
{
    const float* xl  = (const float*)d_in[0];
    const float* xh  = (const float*)d_in[1];
    const float* te  = (const float*)d_in[2];
    const float* Wq  = (const float*)d_in[3];
    const float* bq  = (const float*)d_in[4];
    const float* Wkh = (const float*)d_in[5];
    const float* bkh = (const float*)d_in[6];
    const float* Wvh = (const float*)d_in[7];
    const float* bvh = (const float*)d_in[8];
    const float* Wo  = (const float*)d_in[9];
    const float* bo  = (const float*)d_in[10];
    const float* Wf1 = (const float*)d_in[11];
    const float* bf1 = (const float*)d_in[12];
    const float* Wf2 = (const float*)d_in[13];
    const float* bf2 = (const float*)d_in[14];
    float* outp = (float*)d_out;

    const int smQkv  = 2 * 128 * HP * 2;                      // 69632
    const int smAttn = 3 * 128 * HP * 2;                      // 104448
    const int smTail = 4 * 128 * HP * 2 + 128 * 132 * 4;      // 206848

    cudaFuncSetAttribute(qkv_kernel,  cudaFuncAttributeMaxDynamicSharedMemorySize, smQkv);
    cudaFuncSetAttribute(attn_kernel, cudaFuncAttributeMaxDynamicSharedMemorySize, smAttn);
    cudaFuncSetAttribute(tail_kernel, cudaFuncAttributeMaxDynamicSharedMemorySize, smTail);

    qkv_kernel<<<dim3(MTOT / 128, 3), 256, smQkv>>>(xl, xh, te, Wq, bq, Wkh, bkh, Wvh, bvh);
    attn_kernel<<<BB * NN, 256, smAttn>>>();
    tail_kernel<<<MTOT / 128, 256, smTail>>>(outp, xl, te, Wo, bo, Wf1, bf1, Wf2, bf2);
}